// round 1
// baseline (speedup 1.0000x reference)
#include <cuda_runtime.h>
#include <cstdint>

#define N_NODES 50000
#define N_EDGES 600000
#define IN_C    256
#define HIDC    128
#define R_REL   7
#define N_LAYERS 3
#define KCONV   1024    /* 7*128 agg + 128 cur */
#define KSPLIT  896

// ---------------- scratch (static device globals; no allocation) ----------------
__device__ __align__(16) float g_cur[N_NODES * HIDC];
__device__ __align__(16) float g_hidden[N_NODES * HIDC];
__device__ __align__(16) float g_agg[(size_t)N_NODES * KSPLIT];
__device__ __align__(16) float g_wstack[N_LAYERS * KCONV * HIDC];
__device__ int   g_cnt[N_NODES * 8];
__device__ __align__(16) float g_invcnt[N_NODES * 8];

// ---------------- W stack: [l][r*128+d][f] = sum_b comp*basis ; rows 896+ = root ----
__global__ void wstack_kernel(const float* __restrict__ comps,
                              const float* __restrict__ bases,
                              const float* __restrict__ roots) {
    int idx = blockIdx.x * blockDim.x + threadIdx.x;
    if (idx >= N_LAYERS * KCONV * HIDC) return;
    int f   = idx & 127;
    int row = (idx >> 7) & (KCONV - 1);
    int l   = idx >> 17;               // KCONV*HIDC = 2^17
    float v;
    if (row < KSPLIT) {
        int r = row >> 7, d = row & 127;
        v = 0.f;
#pragma unroll
        for (int b = 0; b < 8; b++)
            v += comps[l * 56 + r * 8 + b] *
                 bases[(((size_t)(l * 8 + b)) * 128 + d) * 128 + f];
    } else {
        int d = row - KSPLIT;
        v = roots[((size_t)l * 128 + d) * 128 + f];
    }
    g_wstack[idx] = v;
}

// ---------------- per-(dst, rel) edge counts (graph-constant) ----------------
__global__ void zero_cnt_kernel() {
    int i = blockIdx.x * blockDim.x + threadIdx.x;
    if (i < N_NODES * 8) g_cnt[i] = 0;
}
__global__ void count_kernel(const int* __restrict__ dst, const int* __restrict__ et, int E) {
    int e = blockIdx.x * blockDim.x + threadIdx.x;
    if (e < E) atomicAdd(&g_cnt[dst[e] * 8 + et[e]], 1);
}
__global__ void invcnt_kernel() {
    int i = blockIdx.x * blockDim.x + threadIdx.x;
    if (i < N_NODES * 8) g_invcnt[i] = 1.f / fmaxf((float)g_cnt[i], 1.f);
}
__global__ void zero_agg_kernel() {
    size_t i = (size_t)blockIdx.x * blockDim.x + threadIdx.x;
    if (i < (size_t)N_NODES * KSPLIT / 4)
        reinterpret_cast<float4*>(g_agg)[i] = make_float4(0.f, 0.f, 0.f, 0.f);
}

// ---------------- edge scatter: warp/edge, float4 red per lane ----------------
__device__ __forceinline__ void red_add_v4(float* p, float4 v) {
    asm volatile("red.global.add.v4.f32 [%0], {%1,%2,%3,%4};"
                 :: "l"(p), "f"(v.x), "f"(v.y), "f"(v.z), "f"(v.w)
                 : "memory");
}
__global__ void scatter_kernel(const int* __restrict__ src, const int* __restrict__ dst,
                               const int* __restrict__ et, int E) {
    int t = blockIdx.x * blockDim.x + threadIdx.x;
    int e = t >> 5;
    if (e >= E) return;
    int lane = t & 31;
    int s = __ldg(src + e);
    int d = __ldg(dst + e);
    int r = __ldg(et + e);
    float4 v = reinterpret_cast<const float4*>(g_cur)[(size_t)s * 32 + lane];
    red_add_v4(g_agg + (size_t)d * KSPLIT + (size_t)r * 128 + lane * 4, v);
}

// ---------------- lin1 GEMM: h = x@W + b ; cur = hidden = temp0*h ----------------
__global__ void __launch_bounds__(256) gemm_lin1(
    const float* __restrict__ X, const float* __restrict__ W,
    const float* __restrict__ bias, const float* __restrict__ tempP, int M) {
    __shared__ float As[16][132];
    __shared__ float Bs[16][128];
    const int rowBase = blockIdx.x * 128;
    const int tid  = threadIdx.x;
    const int tRow = tid >> 4, tCol = tid & 15;
    float acc[8][8];
#pragma unroll
    for (int i = 0; i < 8; i++)
#pragma unroll
        for (int j = 0; j < 8; j++) acc[i][j] = 0.f;

    for (int k0 = 0; k0 < IN_C; k0 += 16) {
#pragma unroll
        for (int ld = 0; ld < 2; ld++) {
            int flat = tid + ld * 256;
            int r = flat >> 2, c4 = (flat & 3) * 4;
            int grow = rowBase + r;
            float4 v = make_float4(0.f, 0.f, 0.f, 0.f);
            if (grow < M)
                v = *reinterpret_cast<const float4*>(X + (size_t)grow * IN_C + k0 + c4);
            As[c4 + 0][r] = v.x; As[c4 + 1][r] = v.y;
            As[c4 + 2][r] = v.z; As[c4 + 3][r] = v.w;
        }
#pragma unroll
        for (int ld = 0; ld < 2; ld++) {
            int flat = tid + ld * 256;
            int r = flat >> 5, c4 = (flat & 31) * 4;
            *reinterpret_cast<float4*>(&Bs[r][c4]) =
                *reinterpret_cast<const float4*>(W + (size_t)(k0 + r) * HIDC + c4);
        }
        __syncthreads();
#pragma unroll
        for (int k = 0; k < 16; k++) {
            float a[8], b[8];
            *reinterpret_cast<float4*>(a)     = *reinterpret_cast<const float4*>(&As[k][tRow * 8]);
            *reinterpret_cast<float4*>(a + 4) = *reinterpret_cast<const float4*>(&As[k][tRow * 8 + 4]);
            *reinterpret_cast<float4*>(b)     = *reinterpret_cast<const float4*>(&Bs[k][tCol * 8]);
            *reinterpret_cast<float4*>(b + 4) = *reinterpret_cast<const float4*>(&Bs[k][tCol * 8 + 4]);
#pragma unroll
            for (int i = 0; i < 8; i++)
#pragma unroll
                for (int j = 0; j < 8; j++)
                    acc[i][j] = fmaf(a[i], b[j], acc[i][j]);
        }
        __syncthreads();
    }
    float t = *tempP;
    int colBase = tCol * 8;
#pragma unroll
    for (int i = 0; i < 8; i++) {
        int row = rowBase + tRow * 8 + i;
        if (row >= M) continue;
        size_t off = (size_t)row * HIDC + colBase;
#pragma unroll
        for (int jj = 0; jj < 2; jj++) {
            float4 v;
            v.x = (acc[i][jj * 4 + 0] + bias[colBase + jj * 4 + 0]) * t;
            v.y = (acc[i][jj * 4 + 1] + bias[colBase + jj * 4 + 1]) * t;
            v.z = (acc[i][jj * 4 + 2] + bias[colBase + jj * 4 + 2]) * t;
            v.w = (acc[i][jj * 4 + 3] + bias[colBase + jj * 4 + 3]) * t;
            *reinterpret_cast<float4*>(g_cur    + off + jj * 4) = v;
            *reinterpret_cast<float4*>(g_hidden + off + jj * 4) = v;
        }
    }
}

// ---------------- conv GEMM: cur = [agg*invcnt | cur] @ Wstack_l + bias ;
//                  optional ReLU ; hidden += temp[l+1]*cur ----------------
template <bool RELU>
__global__ void __launch_bounds__(256) gemm_conv(
    int l, const float* __restrict__ bias, const float* __restrict__ tempP, int M) {
    __shared__ float As[16][132];
    __shared__ float Bs[16][128];
    const float* __restrict__ B = g_wstack + (size_t)l * KCONV * HIDC;
    const int rowBase = blockIdx.x * 128;
    const int tid  = threadIdx.x;
    const int tRow = tid >> 4, tCol = tid & 15;
    float acc[8][8];
#pragma unroll
    for (int i = 0; i < 8; i++)
#pragma unroll
        for (int j = 0; j < 8; j++) acc[i][j] = 0.f;

    for (int k0 = 0; k0 < KCONV; k0 += 16) {
#pragma unroll
        for (int ld = 0; ld < 2; ld++) {
            int flat = tid + ld * 256;
            int r = flat >> 2, c4 = (flat & 3) * 4;
            int grow = rowBase + r;
            int k = k0 + c4;
            float4 v = make_float4(0.f, 0.f, 0.f, 0.f);
            if (grow < M) {
                if (k < KSPLIT) {
                    v = *reinterpret_cast<const float4*>(g_agg + (size_t)grow * KSPLIT + k);
                    float s = g_invcnt[grow * 8 + (k >> 7)];
                    v.x *= s; v.y *= s; v.z *= s; v.w *= s;
                } else {
                    v = *reinterpret_cast<const float4*>(g_cur + (size_t)grow * HIDC + (k - KSPLIT));
                }
            }
            As[c4 + 0][r] = v.x; As[c4 + 1][r] = v.y;
            As[c4 + 2][r] = v.z; As[c4 + 3][r] = v.w;
        }
#pragma unroll
        for (int ld = 0; ld < 2; ld++) {
            int flat = tid + ld * 256;
            int r = flat >> 5, c4 = (flat & 31) * 4;
            *reinterpret_cast<float4*>(&Bs[r][c4]) =
                *reinterpret_cast<const float4*>(B + (size_t)(k0 + r) * HIDC + c4);
        }
        __syncthreads();
#pragma unroll
        for (int k = 0; k < 16; k++) {
            float a[8], b[8];
            *reinterpret_cast<float4*>(a)     = *reinterpret_cast<const float4*>(&As[k][tRow * 8]);
            *reinterpret_cast<float4*>(a + 4) = *reinterpret_cast<const float4*>(&As[k][tRow * 8 + 4]);
            *reinterpret_cast<float4*>(b)     = *reinterpret_cast<const float4*>(&Bs[k][tCol * 8]);
            *reinterpret_cast<float4*>(b + 4) = *reinterpret_cast<const float4*>(&Bs[k][tCol * 8 + 4]);
#pragma unroll
            for (int i = 0; i < 8; i++)
#pragma unroll
                for (int j = 0; j < 8; j++)
                    acc[i][j] = fmaf(a[i], b[j], acc[i][j]);
        }
        __syncthreads();
    }
    float t = *tempP;
    int colBase = tCol * 8;
#pragma unroll
    for (int i = 0; i < 8; i++) {
        int row = rowBase + tRow * 8 + i;
        if (row >= M) continue;
        size_t off = (size_t)row * HIDC + colBase;
#pragma unroll
        for (int jj = 0; jj < 2; jj++) {
            float4 v;
            v.x = acc[i][jj * 4 + 0] + bias[colBase + jj * 4 + 0];
            v.y = acc[i][jj * 4 + 1] + bias[colBase + jj * 4 + 1];
            v.z = acc[i][jj * 4 + 2] + bias[colBase + jj * 4 + 2];
            v.w = acc[i][jj * 4 + 3] + bias[colBase + jj * 4 + 3];
            if (RELU) {
                v.x = fmaxf(v.x, 0.f); v.y = fmaxf(v.y, 0.f);
                v.z = fmaxf(v.z, 0.f); v.w = fmaxf(v.w, 0.f);
            }
            *reinterpret_cast<float4*>(g_cur + off + jj * 4) = v;
            float4 h = *reinterpret_cast<float4*>(g_hidden + off + jj * 4);
            h.x = fmaf(t, v.x, h.x); h.y = fmaf(t, v.y, h.y);
            h.z = fmaf(t, v.z, h.z); h.w = fmaf(t, v.w, h.w);
            *reinterpret_cast<float4*>(g_hidden + off + jj * 4) = h;
        }
    }
}

// ---------------- lin2: out = hidden @ W2 + b2 (warp per row) ----------------
__global__ void lin2_kernel(const float* __restrict__ W, const float* __restrict__ B,
                            float* __restrict__ out, int M) {
    int t = blockIdx.x * blockDim.x + threadIdx.x;
    int rowi = t >> 5, lane = t & 31;
    if (rowi >= M) return;
    float4 h = reinterpret_cast<const float4*>(g_hidden)[(size_t)rowi * 32 + lane];
    int k = lane * 4;
    float a0 = h.x * W[k * 2]     + h.y * W[(k + 1) * 2]     + h.z * W[(k + 2) * 2]     + h.w * W[(k + 3) * 2];
    float a1 = h.x * W[k * 2 + 1] + h.y * W[(k + 1) * 2 + 1] + h.z * W[(k + 2) * 2 + 1] + h.w * W[(k + 3) * 2 + 1];
#pragma unroll
    for (int o = 16; o > 0; o >>= 1) {
        a0 += __shfl_down_sync(0xffffffff, a0, o);
        a1 += __shfl_down_sync(0xffffffff, a1, o);
    }
    if (lane == 0) {
        out[rowi * 2]     = a0 + B[0];
        out[rowi * 2 + 1] = a1 + B[1];
    }
}

// ---------------- launch ----------------
extern "C" void kernel_launch(void* const* d_in, const int* in_sizes, int n_in,
                              void* d_out, int out_size) {
    const float* x     = (const float*)d_in[0];
    const int*   ei    = (const int*)d_in[1];
    const int*   et    = (const int*)d_in[2];
    const float* temp  = (const float*)d_in[3];
    const float* l1w   = (const float*)d_in[4];
    const float* l1b   = (const float*)d_in[5];
    const float* l2w   = (const float*)d_in[6];
    const float* l2b   = (const float*)d_in[7];
    const float* comps = (const float*)d_in[8];
    const float* bases = (const float*)d_in[9];
    const float* roots = (const float*)d_in[10];
    const float* cbias = (const float*)d_in[11];
    float* out = (float*)d_out;

    const int E = in_sizes[2];
    const int M = in_sizes[0] / IN_C;
    const int* src = ei;
    const int* dst = ei + E;

    wstack_kernel<<<(N_LAYERS * KCONV * HIDC + 255) / 256, 256>>>(comps, bases, roots);
    zero_cnt_kernel<<<(N_NODES * 8 + 255) / 256, 256>>>();
    count_kernel<<<(E + 255) / 256, 256>>>(dst, et, E);
    invcnt_kernel<<<(N_NODES * 8 + 255) / 256, 256>>>();

    gemm_lin1<<<(M + 127) / 128, 256>>>(x, l1w, l1b, temp, M);

    for (int l = 0; l < N_LAYERS; l++) {
        zero_agg_kernel<<<(int)(((size_t)N_NODES * KSPLIT / 4 + 255) / 256), 256>>>();
        scatter_kernel<<<(int)(((size_t)E * 32 + 255) / 256), 256>>>(src, dst, et, E);
        const float* bptr = cbias + l * HIDC;
        const float* tptr = temp + l + 1;
        if (l < N_LAYERS - 1)
            gemm_conv<true><<<(M + 127) / 128, 256>>>(l, bptr, tptr, M);
        else
            gemm_conv<false><<<(M + 127) / 128, 256>>>(l, bptr, tptr, M);
    }

    lin2_kernel<<<(int)(((size_t)M * 32 + 255) / 256), 256>>>(l2w, l2b, out, M);
}

// round 3
// speedup vs baseline: 1.5960x; 1.5960x over previous
#include <cuda_runtime.h>
#include <cstdint>

#define NN      50000
#define NPADT   391
#define NPAD    (NPADT*128)    /* 50048 */
#define HIDC    128
#define INC     256
#define LAYERS  3

// ---------------- device scratch (static globals; no allocation) ----------------
__device__ __align__(16) float g_y[(size_t)NPAD * 896];     // per-relation transformed features
__device__ __align__(16) float g_next[(size_t)NPAD * 128];
__device__ __align__(16) float g_hidden[(size_t)NPAD * 128];
__device__ __align__(16) float g_cur[(size_t)NPAD * 128];
__device__ __align__(16) float g_wcat[LAYERS * 8 * 128 * 128];  // [l][fb][f][k]
__device__ __align__(16) float g_l1t[128 * 256];                // [f][k]
__device__ int   g_cnt[NPAD * 8];
__device__ float g_invcnt[NPAD * 8];

// ---------------- helpers ----------------
__device__ __forceinline__ void split_tf32(float v, uint32_t& hi, uint32_t& lo) {
    uint32_t h;
    asm("cvt.rna.tf32.f32 %0, %1;" : "=r"(h) : "f"(v));
    float r = v - __uint_as_float(h);
    uint32_t l;
    asm("cvt.rna.tf32.f32 %0, %1;" : "=r"(l) : "f"(r));
    hi = h; lo = l;
}
__device__ __forceinline__ void mma1688(float* d, const uint32_t* a, const uint32_t* b) {
    asm volatile(
        "mma.sync.aligned.m16n8k8.row.col.f32.tf32.tf32.f32 "
        "{%0,%1,%2,%3}, {%4,%5,%6,%7}, {%8,%9}, {%0,%1,%2,%3};"
        : "+f"(d[0]), "+f"(d[1]), "+f"(d[2]), "+f"(d[3])
        : "r"(a[0]), "r"(a[1]), "r"(a[2]), "r"(a[3]), "r"(b[0]), "r"(b[1]));
}

// ---------------- prep: conv weights [l][fb][f][k] ----------------
__global__ void conv_w_kernel(const float* __restrict__ comps,
                              const float* __restrict__ bases,
                              const float* __restrict__ roots) {
    int idx = blockIdx.x * blockDim.x + threadIdx.x;
    if (idx >= LAYERS * 8 * 16384) return;
    int l  = idx >> 17;
    int fb = (idx >> 14) & 7;
    int e  = idx & 16383;
    int f  = e >> 7;
    int k  = e & 127;
    float v;
    if (fb < 7) {
        v = 0.f;
#pragma unroll
        for (int b = 0; b < 8; b++)
            v += comps[l * 56 + fb * 8 + b] * bases[((size_t)(l * 8 + b) * 128 + k) * 128 + f];
    } else {
        v = roots[((size_t)l * 128 + k) * 128 + f];
    }
    g_wcat[idx] = v;
}

// ---------------- prep: lin1 weight transpose [f][k] ----------------
__global__ void l1t_kernel(const float* __restrict__ w) {
    int idx = blockIdx.x * blockDim.x + threadIdx.x;
    if (idx >= 128 * 256) return;
    int f = idx >> 8, k = idx & 255;
    g_l1t[idx] = w[k * 128 + f];
}

// ---------------- counts ----------------
__global__ void zero_cnt_kernel() {
    int i = blockIdx.x * blockDim.x + threadIdx.x;
    if (i < NPAD * 8) g_cnt[i] = 0;
}
__global__ void count_kernel(const int* __restrict__ dst, const int* __restrict__ et, int E) {
    int e = blockIdx.x * blockDim.x + threadIdx.x;
    if (e < E) atomicAdd(&g_cnt[dst[e] * 8 + et[e]], 1);
}
__global__ void invcnt_kernel() {
    int i = blockIdx.x * blockDim.x + threadIdx.x;
    if (i < NPAD * 8) g_invcnt[i] = 1.f / fmaxf((float)g_cnt[i], 1.f);
}

// ---------------- tf32x3 mma.sync GEMM ----------------
// D[row=node, col=f] = sum_k A[row,k] * W[fb][col,k]
// block: 128x128 out tile; 8 warps, warp tile m64 x n32; KCHUNKS*128 total K
// MODE 0: conv  -> fb<7: g_y[row, fb*128+col] = acc ; fb==7: g_next = acc + bias
// MODE 1: lin1  -> g_hidden = g_cur = (acc + bias) * temp[0]
template <int KCHUNKS, int MODE>
__global__ void __launch_bounds__(256) gemm_mma(
    const float* __restrict__ A,    // [*, KCHUNKS*128] row-major
    const float* __restrict__ W,    // [gridDim.y][128][KCHUNKS*128]
    const float* __restrict__ bias,
    const float* __restrict__ tempP,
    int Mrows) {
    extern __shared__ float smem[];
    float (*sA)[132] = (float (*)[132])smem;
    float (*sB)[132] = (float (*)[132])(smem + 128 * 132);

    const int tid  = threadIdx.x;
    const int lane = tid & 31, wid = tid >> 5;
    const int wm = wid & 1, wn = wid >> 1;           // 2 x 4 warp grid
    const int tile = blockIdx.x, fbid = blockIdx.y;
    const int ldA = KCHUNKS * 128;

    float acc[4][4][4];
#pragma unroll
    for (int mi = 0; mi < 4; mi++)
#pragma unroll
        for (int ni = 0; ni < 4; ni++)
#pragma unroll
            for (int j = 0; j < 4; j++) acc[mi][ni][j] = 0.f;

    for (int kc = 0; kc < KCHUNKS; kc++) {
        // load A tile [128][128]
#pragma unroll
        for (int i = tid; i < 4096; i += 256) {
            int r = i >> 5, c4 = (i & 31) * 4;
            int grow = tile * 128 + r;
            float4 v = make_float4(0.f, 0.f, 0.f, 0.f);
            if (grow < Mrows)
                v = *(const float4*)(A + (size_t)grow * ldA + kc * 128 + c4);
            sA[r][c4] = v.x; sA[r][c4 + 1] = v.y; sA[r][c4 + 2] = v.z; sA[r][c4 + 3] = v.w;
        }
        // load B tile [128 f][128 k]
        const float* Wb = W + (size_t)fbid * 128 * ldA + kc * 128;
#pragma unroll
        for (int i = tid; i < 4096; i += 256) {
            int r = i >> 5, c4 = (i & 31) * 4;
            float4 v = *(const float4*)(Wb + (size_t)r * ldA + c4);
            sB[r][c4] = v.x; sB[r][c4 + 1] = v.y; sB[r][c4 + 2] = v.z; sB[r][c4 + 3] = v.w;
        }
        __syncthreads();

#pragma unroll
        for (int k0 = 0; k0 < 128; k0 += 8) {
            uint32_t ah[4][4], al[4][4], bh[4][2], bl[4][2];
#pragma unroll
            for (int mi = 0; mi < 4; mi++) {
                int r = wm * 64 + mi * 16 + (lane >> 2);
                int c = k0 + (lane & 3);
                split_tf32(sA[r][c],         ah[mi][0], al[mi][0]);
                split_tf32(sA[r + 8][c],     ah[mi][1], al[mi][1]);
                split_tf32(sA[r][c + 4],     ah[mi][2], al[mi][2]);
                split_tf32(sA[r + 8][c + 4], ah[mi][3], al[mi][3]);
            }
#pragma unroll
            for (int ni = 0; ni < 4; ni++) {
                int fr = wn * 32 + ni * 8 + (lane >> 2);
                int c  = k0 + (lane & 3);
                split_tf32(sB[fr][c],     bh[ni][0], bl[ni][0]);
                split_tf32(sB[fr][c + 4], bh[ni][1], bl[ni][1]);
            }
#pragma unroll
            for (int mi = 0; mi < 4; mi++)
#pragma unroll
                for (int ni = 0; ni < 4; ni++) {
                    mma1688(acc[mi][ni], ah[mi], bh[ni]);
                    mma1688(acc[mi][ni], al[mi], bh[ni]);
                    mma1688(acc[mi][ni], ah[mi], bl[ni]);
                }
        }
        __syncthreads();
    }

    // epilogue
    float t0 = (MODE == 1) ? __ldg(tempP) : 0.f;
#pragma unroll
    for (int mi = 0; mi < 4; mi++) {
#pragma unroll
        for (int ni = 0; ni < 4; ni++) {
            int row = tile * 128 + wm * 64 + mi * 16 + (lane >> 2);
            int col = wn * 32 + ni * 8 + (lane & 3) * 2;
            float* a4 = acc[mi][ni];
            if (MODE == 0) {
                if (fbid < 7) {
                    *(float2*)&g_y[(size_t)row * 896 + fbid * 128 + col] =
                        make_float2(a4[0], a4[1]);
                    *(float2*)&g_y[(size_t)(row + 8) * 896 + fbid * 128 + col] =
                        make_float2(a4[2], a4[3]);
                } else {
                    float b0 = bias[col], b1 = bias[col + 1];
                    *(float2*)&g_next[(size_t)row * 128 + col] =
                        make_float2(a4[0] + b0, a4[1] + b1);
                    *(float2*)&g_next[(size_t)(row + 8) * 128 + col] =
                        make_float2(a4[2] + b0, a4[3] + b1);
                }
            } else {
                float b0 = bias[col], b1 = bias[col + 1];
                float2 v0 = make_float2((a4[0] + b0) * t0, (a4[1] + b1) * t0);
                float2 v1 = make_float2((a4[2] + b0) * t0, (a4[3] + b1) * t0);
                *(float2*)&g_hidden[(size_t)row * 128 + col] = v0;
                *(float2*)&g_hidden[(size_t)(row + 8) * 128 + col] = v1;
                *(float2*)&g_cur[(size_t)row * 128 + col] = v0;
                *(float2*)&g_cur[(size_t)(row + 8) * 128 + col] = v1;
            }
        }
    }
}

// ---------------- scatter: next[dst] += invcnt[dst,rel] * Y[src, rel*128:+128] ----------------
__device__ __forceinline__ void red_add_v4(float* p, float4 v) {
    asm volatile("red.global.add.v4.f32 [%0], {%1,%2,%3,%4};"
                 :: "l"(p), "f"(v.x), "f"(v.y), "f"(v.z), "f"(v.w) : "memory");
}
__global__ void scatter_kernel(const int* __restrict__ src, const int* __restrict__ dst,
                               const int* __restrict__ et, int E) {
    int t = blockIdx.x * blockDim.x + threadIdx.x;
    int e = t >> 5;
    if (e >= E) return;
    int lane = t & 31;
    int s = __ldg(src + e), d = __ldg(dst + e), r = __ldg(et + e);
    float sc = g_invcnt[d * 8 + r];
    float4 v = ((const float4*)(g_y + (size_t)s * 896 + r * 128))[lane];
    v.x *= sc; v.y *= sc; v.z *= sc; v.w *= sc;
    red_add_v4(g_next + (size_t)d * 128 + lane * 4, v);
}

// ---------------- finalize: relu, hidden accum, next-layer cur ----------------
__global__ void finalize_kernel(const float* __restrict__ tempP, int relu, int wcur) {
    int idx = blockIdx.x * blockDim.x + threadIdx.x;
    if (idx >= NPAD * 128) return;
    float v = g_next[idx];
    if (relu) v = fmaxf(v, 0.f);
    g_hidden[idx] = fmaf(__ldg(tempP), v, g_hidden[idx]);
    if (wcur) g_cur[idx] = v;
}

// ---------------- lin2 ----------------
__global__ void lin2_kernel(const float* __restrict__ W, const float* __restrict__ B,
                            float* __restrict__ out, int M) {
    int t = blockIdx.x * blockDim.x + threadIdx.x;
    int rowi = t >> 5, lane = t & 31;
    if (rowi >= M) return;
    float4 h = ((const float4*)g_hidden)[(size_t)rowi * 32 + lane];
    int k = lane * 4;
    float a0 = h.x * W[k * 2]     + h.y * W[(k + 1) * 2]     + h.z * W[(k + 2) * 2]     + h.w * W[(k + 3) * 2];
    float a1 = h.x * W[k * 2 + 1] + h.y * W[(k + 1) * 2 + 1] + h.z * W[(k + 2) * 2 + 1] + h.w * W[(k + 3) * 2 + 1];
#pragma unroll
    for (int o = 16; o > 0; o >>= 1) {
        a0 += __shfl_down_sync(0xffffffff, a0, o);
        a1 += __shfl_down_sync(0xffffffff, a1, o);
    }
    if (lane == 0) {
        out[rowi * 2]     = a0 + B[0];
        out[rowi * 2 + 1] = a1 + B[1];
    }
}

// ---------------- launch ----------------
extern "C" void kernel_launch(void* const* d_in, const int* in_sizes, int n_in,
                              void* d_out, int out_size) {
    const float* x     = (const float*)d_in[0];
    const int*   ei    = (const int*)d_in[1];
    const int*   et    = (const int*)d_in[2];
    const float* temp  = (const float*)d_in[3];
    const float* l1w   = (const float*)d_in[4];
    const float* l1b   = (const float*)d_in[5];
    const float* l2w   = (const float*)d_in[6];
    const float* l2b   = (const float*)d_in[7];
    const float* comps = (const float*)d_in[8];
    const float* bases = (const float*)d_in[9];
    const float* roots = (const float*)d_in[10];
    const float* cbias = (const float*)d_in[11];
    float* out = (float*)d_out;

    const int E = in_sizes[2];
    const int M = in_sizes[0] / INC;
    const int* src = ei;
    const int* dst = ei + E;

    const int SMEM_BYTES = 2 * 128 * 132 * 4;   // 135168
    static bool attr_set = false;
    if (!attr_set) {
        cudaFuncSetAttribute(gemm_mma<2, 1>, cudaFuncAttributeMaxDynamicSharedMemorySize, SMEM_BYTES);
        cudaFuncSetAttribute(gemm_mma<1, 0>, cudaFuncAttributeMaxDynamicSharedMemorySize, SMEM_BYTES);
        attr_set = true;
    }

    float* wcat_ptr; cudaGetSymbolAddress((void**)&wcat_ptr, g_wcat);
    float* l1t_ptr;  cudaGetSymbolAddress((void**)&l1t_ptr, g_l1t);
    float* cur_ptr;  cudaGetSymbolAddress((void**)&cur_ptr, g_cur);

    // prep
    conv_w_kernel<<<(LAYERS * 8 * 16384 + 255) / 256, 256>>>(comps, bases, roots);
    l1t_kernel<<<(128 * 256 + 255) / 256, 256>>>(l1w);
    zero_cnt_kernel<<<(NPAD * 8 + 255) / 256, 256>>>();
    count_kernel<<<(E + 255) / 256, 256>>>(dst, et, E);
    invcnt_kernel<<<(NPAD * 8 + 255) / 256, 256>>>();

    // lin1: hidden = cur = temp0*(x@W1 + b1)
    gemm_mma<2, 1><<<dim3(NPADT, 1), 256, SMEM_BYTES>>>(x, l1t_ptr, l1b, temp, M);

    for (int l = 0; l < LAYERS; l++) {
        gemm_mma<1, 0><<<dim3(NPADT, 8), 256, SMEM_BYTES>>>(
            cur_ptr, wcat_ptr + (size_t)l * 8 * 16384, cbias + l * HIDC, temp, NPAD);
        scatter_kernel<<<(int)(((size_t)E * 32 + 255) / 256), 256>>>(src, dst, et, E);
        finalize_kernel<<<(NPAD * 128 + 255) / 256, 256>>>(
            temp + l + 1, (l < LAYERS - 1) ? 1 : 0, (l < LAYERS - 1) ? 1 : 0);
    }

    lin2_kernel<<<(int)(((size_t)M * 32 + 255) / 256), 256>>>(l2w, l2b, out, M);
}

// round 4
// speedup vs baseline: 1.6376x; 1.0260x over previous
#include <cuda_runtime.h>
#include <cstdint>

#define NN      50000
#define NPADT   391
#define NPAD    (NPADT*128)    /* 50048 */
#define HIDC    128
#define INC     256
#define LAYERS  3
#define NBINS   (NPAD*8)       /* 400384 = 391*1024 */
#define EMAX    600000

// ---------------- device scratch (static globals; no allocation) ----------------
__device__ __align__(16) float g_agg[(size_t)NPAD * 896];
__device__ __align__(16) float g_hidden[(size_t)NPAD * 128];
__device__ __align__(16) float g_cur[(size_t)NPAD * 128];
__device__ __align__(16) float g_wcat[LAYERS * 128 * 1024];   // [l][f][k]
__device__ __align__(16) float g_l1t[128 * 256];              // [f][k]
__device__ int   g_cnt[NBINS];
__device__ float g_invcnt[NBINS];
__device__ int   g_off[NBINS];
__device__ int   g_cursor[NBINS];
__device__ int   g_bsum[NBINS / 1024];
__device__ int   g_bsumx[NBINS / 1024];
__device__ int   g_esrc[EMAX];

// ---------------- helpers ----------------
__device__ __forceinline__ void split_tf32(float v, uint32_t& hi, uint32_t& lo) {
    uint32_t h;
    asm("cvt.rna.tf32.f32 %0, %1;" : "=r"(h) : "f"(v));
    float r = v - __uint_as_float(h);
    uint32_t l;
    asm("cvt.rna.tf32.f32 %0, %1;" : "=r"(l) : "f"(r));
    hi = h; lo = l;
}
__device__ __forceinline__ void mma1688(float* d, const uint32_t* a, const uint32_t* b) {
    asm volatile(
        "mma.sync.aligned.m16n8k8.row.col.f32.tf32.tf32.f32 "
        "{%0,%1,%2,%3}, {%4,%5,%6,%7}, {%8,%9}, {%0,%1,%2,%3};"
        : "+f"(d[0]), "+f"(d[1]), "+f"(d[2]), "+f"(d[3])
        : "r"(a[0]), "r"(a[1]), "r"(a[2]), "r"(a[3]), "r"(b[0]), "r"(b[1]));
}

// ---------------- prep: conv weights [l][f][k], k = r*128+d (r=7 -> root) ---------
__global__ void conv_w_kernel(const float* __restrict__ comps,
                              const float* __restrict__ bases,
                              const float* __restrict__ roots) {
    int idx = blockIdx.x * blockDim.x + threadIdx.x;
    if (idx >= LAYERS * 128 * 1024) return;
    int l   = idx >> 17;
    int rem = idx & 131071;
    int f   = rem >> 10;
    int k   = rem & 1023;
    int r   = k >> 7, d = k & 127;
    float v;
    if (r < 7) {
        v = 0.f;
#pragma unroll
        for (int b = 0; b < 8; b++)
            v += comps[l * 56 + r * 8 + b] * bases[((size_t)(l * 8 + b) * 128 + d) * 128 + f];
    } else {
        v = roots[((size_t)l * 128 + d) * 128 + f];
    }
    g_wcat[idx] = v;
}

// ---------------- prep: lin1 weight transpose [f][k] ----------------
__global__ void l1t_kernel(const float* __restrict__ w) {
    int idx = blockIdx.x * blockDim.x + threadIdx.x;
    if (idx >= 128 * 256) return;
    int f = idx >> 8, k = idx & 255;
    g_l1t[idx] = w[k * 128 + f];
}

// ---------------- counts / invcnt ----------------
__global__ void zero_cnt_kernel() {
    int i = blockIdx.x * blockDim.x + threadIdx.x;
    if (i < NBINS) g_cnt[i] = 0;
}
__global__ void count_kernel(const int* __restrict__ dst, const int* __restrict__ et, int E) {
    int e = blockIdx.x * blockDim.x + threadIdx.x;
    if (e < E) atomicAdd(&g_cnt[dst[e] * 8 + et[e]], 1);
}
__global__ void invcnt_kernel() {
    int i = blockIdx.x * blockDim.x + threadIdx.x;
    if (i < NBINS) g_invcnt[i] = 1.f / fmaxf((float)g_cnt[i], 1.f);
}

// ---------------- exclusive scan over NBINS = 391 * 1024 ----------------
__global__ void scan1_kernel() {
    __shared__ int s[1024];
    int tid = threadIdx.x;
    int i   = blockIdx.x * 1024 + tid;
    int v   = g_cnt[i];
    s[tid] = v;
    __syncthreads();
#pragma unroll
    for (int o = 1; o < 1024; o <<= 1) {
        int t = (tid >= o) ? s[tid - o] : 0;
        __syncthreads();
        s[tid] += t;
        __syncthreads();
    }
    g_off[i] = s[tid] - v;
    if (tid == 1023) g_bsum[blockIdx.x] = s[1023];
}
__global__ void scan2_kernel() {
    __shared__ int s[512];
    int tid = threadIdx.x;
    int v = (tid < NBINS / 1024) ? g_bsum[tid] : 0;
    s[tid] = v;
    __syncthreads();
#pragma unroll
    for (int o = 1; o < 512; o <<= 1) {
        int t = (tid >= o) ? s[tid - o] : 0;
        __syncthreads();
        s[tid] += t;
        __syncthreads();
    }
    if (tid < NBINS / 1024) g_bsumx[tid] = s[tid] - v;
}
__global__ void scan3_kernel() {
    int i = blockIdx.x * blockDim.x + threadIdx.x;
    if (i >= NBINS) return;
    int o = g_off[i] + g_bsumx[i >> 10];
    g_off[i] = o;
    g_cursor[i] = o;
}

// ---------------- counting-sort scatter: g_esrc sorted by (dst,rel) ----------------
__global__ void sort_kernel(const int* __restrict__ src, const int* __restrict__ dst,
                            const int* __restrict__ et, int E) {
    int e = blockIdx.x * blockDim.x + threadIdx.x;
    if (e >= E) return;
    int key = dst[e] * 8 + et[e];
    int pos = atomicAdd(&g_cursor[key], 1);
    g_esrc[pos] = src[e];
}

// ---------------- aggregation: warp per node; agg[d, r*128:] = invcnt * sum cur[src] ---
__global__ void agg_kernel(int M) {
    int t = blockIdx.x * blockDim.x + threadIdx.x;
    int d = t >> 5, lane = t & 31;
    if (d >= M) return;
    const float4* cur4 = (const float4*)g_cur;
    float* outp = g_agg + (size_t)d * 896;
#pragma unroll
    for (int r = 0; r < 7; r++) {
        int key = d * 8 + r;
        int st = g_off[key];
        int n  = g_cnt[key];
        float4 acc = make_float4(0.f, 0.f, 0.f, 0.f);
        for (int i = 0; i < n; i++) {
            int s = __ldg(&g_esrc[st + i]);
            float4 v = cur4[(size_t)s * 32 + lane];
            acc.x += v.x; acc.y += v.y; acc.z += v.z; acc.w += v.w;
        }
        float ic = g_invcnt[key];
        ((float4*)(outp + r * 128))[lane] =
            make_float4(acc.x * ic, acc.y * ic, acc.z * ic, acc.w * ic);
    }
}

// ---------------- tf32x3 mma.sync GEMM ----------------
// MODE 1: lin1   A = x [M,256], K=256.  hidden = cur = (acc+bias)*temp[0]
// MODE 2: conv   A = [agg | cur] (K=1024, kc 7 = cur). Epilogue fused:
//                v = acc+bias; relu?; hidden += temp*v; wcur? cur = v
template <int KCHUNKS, int MODE>
__global__ void __launch_bounds__(256) gemm_mma(
    const float* __restrict__ A,
    const float* __restrict__ W,
    const float* __restrict__ bias,
    const float* __restrict__ tempP,
    int Mrows, int relu, int wcur) {
    extern __shared__ float smem[];
    float (*sA)[132] = (float (*)[132])smem;
    float (*sB)[132] = (float (*)[132])(smem + 128 * 132);

    const int tid  = threadIdx.x;
    const int lane = tid & 31, wid = tid >> 5;
    const int wm = wid & 1, wn = wid >> 1;
    const int tile = blockIdx.x;
    const int ldA = KCHUNKS * 128;

    float acc[4][4][4];
#pragma unroll
    for (int mi = 0; mi < 4; mi++)
#pragma unroll
        for (int ni = 0; ni < 4; ni++)
#pragma unroll
            for (int j = 0; j < 4; j++) acc[mi][ni][j] = 0.f;

    for (int kc = 0; kc < KCHUNKS; kc++) {
        // A tile
#pragma unroll
        for (int i = tid; i < 4096; i += 256) {
            int r = i >> 5, c4 = (i & 31) * 4;
            int grow = tile * 128 + r;
            float4 v = make_float4(0.f, 0.f, 0.f, 0.f);
            if (grow < Mrows) {
                if (MODE == 2) {
                    if (kc < 7)
                        v = *(const float4*)(g_agg + (size_t)grow * 896 + kc * 128 + c4);
                    else
                        v = *(const float4*)(g_cur + (size_t)grow * 128 + c4);
                } else {
                    v = *(const float4*)(A + (size_t)grow * ldA + kc * 128 + c4);
                }
            }
            sA[r][c4] = v.x; sA[r][c4 + 1] = v.y; sA[r][c4 + 2] = v.z; sA[r][c4 + 3] = v.w;
        }
        // B tile [f][k]
        const float* Wb = W + kc * 128;
#pragma unroll
        for (int i = tid; i < 4096; i += 256) {
            int r = i >> 5, c4 = (i & 31) * 4;
            float4 v = *(const float4*)(Wb + (size_t)r * ldA + c4);
            sB[r][c4] = v.x; sB[r][c4 + 1] = v.y; sB[r][c4 + 2] = v.z; sB[r][c4 + 3] = v.w;
        }
        __syncthreads();

#pragma unroll
        for (int k0 = 0; k0 < 128; k0 += 8) {
            uint32_t ah[4][4], al[4][4], bh[4][2], bl[4][2];
#pragma unroll
            for (int mi = 0; mi < 4; mi++) {
                int r = wm * 64 + mi * 16 + (lane >> 2);
                int c = k0 + (lane & 3);
                split_tf32(sA[r][c],         ah[mi][0], al[mi][0]);
                split_tf32(sA[r + 8][c],     ah[mi][1], al[mi][1]);
                split_tf32(sA[r][c + 4],     ah[mi][2], al[mi][2]);
                split_tf32(sA[r + 8][c + 4], ah[mi][3], al[mi][3]);
            }
#pragma unroll
            for (int ni = 0; ni < 4; ni++) {
                int fr = wn * 32 + ni * 8 + (lane >> 2);
                int c  = k0 + (lane & 3);
                split_tf32(sB[fr][c],     bh[ni][0], bl[ni][0]);
                split_tf32(sB[fr][c + 4], bh[ni][1], bl[ni][1]);
            }
#pragma unroll
            for (int mi = 0; mi < 4; mi++)
#pragma unroll
                for (int ni = 0; ni < 4; ni++) {
                    mma1688(acc[mi][ni], ah[mi], bh[ni]);
                    mma1688(acc[mi][ni], al[mi], bh[ni]);
                    mma1688(acc[mi][ni], ah[mi], bl[ni]);
                }
        }
        __syncthreads();
    }

    // epilogue
    float t0 = __ldg(tempP);
#pragma unroll
    for (int mi = 0; mi < 4; mi++) {
#pragma unroll
        for (int ni = 0; ni < 4; ni++) {
            int row = tile * 128 + wm * 64 + mi * 16 + (lane >> 2);
            int col = wn * 32 + ni * 8 + (lane & 3) * 2;
            float* a4 = acc[mi][ni];
            float b0 = bias[col], b1 = bias[col + 1];
            if (MODE == 1) {
                float2 v0 = make_float2((a4[0] + b0) * t0, (a4[1] + b1) * t0);
                float2 v1 = make_float2((a4[2] + b0) * t0, (a4[3] + b1) * t0);
                *(float2*)&g_hidden[(size_t)row * 128 + col] = v0;
                *(float2*)&g_hidden[(size_t)(row + 8) * 128 + col] = v1;
                *(float2*)&g_cur[(size_t)row * 128 + col] = v0;
                *(float2*)&g_cur[(size_t)(row + 8) * 128 + col] = v1;
            } else {
#pragma unroll
                for (int half = 0; half < 2; half++) {
                    int rr = row + half * 8;
                    float vx = a4[half * 2 + 0] + b0;
                    float vy = a4[half * 2 + 1] + b1;
                    if (relu) { vx = fmaxf(vx, 0.f); vy = fmaxf(vy, 0.f); }
                    float2 h = *(float2*)&g_hidden[(size_t)rr * 128 + col];
                    h.x = fmaf(t0, vx, h.x);
                    h.y = fmaf(t0, vy, h.y);
                    *(float2*)&g_hidden[(size_t)rr * 128 + col] = h;
                    if (wcur)
                        *(float2*)&g_cur[(size_t)rr * 128 + col] = make_float2(vx, vy);
                }
            }
        }
    }
}

// ---------------- lin2 ----------------
__global__ void lin2_kernel(const float* __restrict__ W, const float* __restrict__ B,
                            float* __restrict__ out, int M) {
    int t = blockIdx.x * blockDim.x + threadIdx.x;
    int rowi = t >> 5, lane = t & 31;
    if (rowi >= M) return;
    float4 h = ((const float4*)g_hidden)[(size_t)rowi * 32 + lane];
    int k = lane * 4;
    float a0 = h.x * W[k * 2]     + h.y * W[(k + 1) * 2]     + h.z * W[(k + 2) * 2]     + h.w * W[(k + 3) * 2];
    float a1 = h.x * W[k * 2 + 1] + h.y * W[(k + 1) * 2 + 1] + h.z * W[(k + 2) * 2 + 1] + h.w * W[(k + 3) * 2 + 1];
#pragma unroll
    for (int o = 16; o > 0; o >>= 1) {
        a0 += __shfl_down_sync(0xffffffff, a0, o);
        a1 += __shfl_down_sync(0xffffffff, a1, o);
    }
    if (lane == 0) {
        out[rowi * 2]     = a0 + B[0];
        out[rowi * 2 + 1] = a1 + B[1];
    }
}

// ---------------- launch ----------------
extern "C" void kernel_launch(void* const* d_in, const int* in_sizes, int n_in,
                              void* d_out, int out_size) {
    const float* x     = (const float*)d_in[0];
    const int*   ei    = (const int*)d_in[1];
    const int*   et    = (const int*)d_in[2];
    const float* temp  = (const float*)d_in[3];
    const float* l1w   = (const float*)d_in[4];
    const float* l1b   = (const float*)d_in[5];
    const float* l2w   = (const float*)d_in[6];
    const float* l2b   = (const float*)d_in[7];
    const float* comps = (const float*)d_in[8];
    const float* bases = (const float*)d_in[9];
    const float* roots = (const float*)d_in[10];
    const float* cbias = (const float*)d_in[11];
    float* out = (float*)d_out;

    const int E = in_sizes[2];
    const int M = in_sizes[0] / INC;
    const int* src = ei;
    const int* dst = ei + E;

    const int SMEM_BYTES = 2 * 128 * 132 * 4;   // 135168
    static bool attr_set = false;
    if (!attr_set) {
        cudaFuncSetAttribute(gemm_mma<2, 1>, cudaFuncAttributeMaxDynamicSharedMemorySize, SMEM_BYTES);
        cudaFuncSetAttribute(gemm_mma<8, 2>, cudaFuncAttributeMaxDynamicSharedMemorySize, SMEM_BYTES);
        attr_set = true;
    }

    float* wcat_ptr; cudaGetSymbolAddress((void**)&wcat_ptr, g_wcat);
    float* l1t_ptr;  cudaGetSymbolAddress((void**)&l1t_ptr, g_l1t);
    float* agg_ptr;  cudaGetSymbolAddress((void**)&agg_ptr, g_agg);

    // prep + counting sort of edges by (dst, rel) — graph-constant, reused all layers
    conv_w_kernel<<<(LAYERS * 128 * 1024 + 255) / 256, 256>>>(comps, bases, roots);
    l1t_kernel<<<(128 * 256 + 255) / 256, 256>>>(l1w);
    zero_cnt_kernel<<<(NBINS + 255) / 256, 256>>>();
    count_kernel<<<(E + 255) / 256, 256>>>(dst, et, E);
    invcnt_kernel<<<(NBINS + 255) / 256, 256>>>();
    scan1_kernel<<<NBINS / 1024, 1024>>>();
    scan2_kernel<<<1, 512>>>();
    scan3_kernel<<<(NBINS + 255) / 256, 256>>>();
    sort_kernel<<<(E + 255) / 256, 256>>>(src, dst, et, E);

    // lin1: hidden = cur = temp0*(x@W1 + b1)
    gemm_mma<2, 1><<<NPADT, 256, SMEM_BYTES>>>(x, l1t_ptr, l1b, temp, M, 0, 0);

    for (int l = 0; l < LAYERS; l++) {
        agg_kernel<<<(M * 32 + 255) / 256, 256>>>(M);
        gemm_mma<8, 2><<<NPADT, 256, SMEM_BYTES>>>(
            agg_ptr, wcat_ptr + (size_t)l * 128 * 1024, cbias + l * HIDC,
            temp + l + 1, M, (l < LAYERS - 1) ? 1 : 0, (l < LAYERS - 1) ? 1 : 0);
    }

    lin2_kernel<<<(M * 32 + 255) / 256, 256>>>(l2w, l2b, out, M);
}